// round 2
// baseline (speedup 1.0000x reference)
#include <cuda_runtime.h>
#include <cuda_bf16.h>
#include <math.h>

#define NB   1024
#define NNUM 16
#define NCAT 16
#define NCH  32
#define NH   64
#define NV   100
#define KSEL 8
#define EPS  1e-5f

// ---------------- scratch (static device globals; no allocs) ----------------
__device__ float g_fe3[NB * NCH * NH];            // 8MB
__device__ float g_impraw[NB * NCH];
__device__ float g_p[NB * NCH];
__device__ int   g_idx[NB * KSEL];
__device__ int   g_cnt[NCH];
__device__ int   g_nodes[NCH * NB];
__device__ int   g_loc[NCH * NB];
__device__ float g_Y[NB * NH];
__device__ float g_adj[(size_t)NCH * NB * NB];    // 128MB slab: S -> E -> An
__device__ int   g_mx[NCH];
__device__ float g_rowsum[NCH * NB];
__device__ float g_Z[NCH];
__device__ float g_dinv[NCH * NB];
__device__ float g_X1[NCH * NB * NH];             // 8MB (X1, then reused for X2)
__device__ float g_T[NCH * NB * NH];              // 8MB
__device__ float g_stats1[NCH * 2];
__device__ float g_stats2[NCH * 2];
__device__ float g_sums[8];
__device__ float g_full[NB * (KSEL + NCH) * NH];  // 10MB
__device__ float g_Hd[NB * NH];
__device__ float g_part[16 * NB * NH];            // 4MB

// ---------------------------------------------------------------------------
__global__ void k_init() {
  int i = threadIdx.x;
  if (i < 8) g_sums[i] = 0.f;
  if (i < NCH) { g_cnt[i] = 0; g_mx[i] = 0; g_Z[i] = 0.f; }
  if (i < NCH * 2) { g_stats1[i] = 0.f; g_stats2[i] = 0.f; }
}

__global__ void k_fe(const float* __restrict__ num_data, const int* __restrict__ cat_data,
                     const float* __restrict__ num_w, const float* __restrict__ num_b,
                     const float* __restrict__ cat_emb) {
  int t = threadIdx.x;
  int b = blockIdx.x >> 1;
  int half = blockIdx.x & 1;
  float s = 0.f, s2 = 0.f;
#pragma unroll
  for (int q = 0; q < 4; q++) {
    int off = t + q * 256;
    int ch = off >> 6, h = off & 63;
    float v;
    if (half == 0) {
      v = num_data[b * NNUM + ch] * num_w[ch * NH + h] + num_b[ch * NH + h];
      v = fmaxf(v, 0.f);
    } else {
      v = cat_emb[((size_t)ch * NV + cat_data[b * NCAT + ch]) * NH + h];
    }
    g_fe3[b * 2048 + half * 1024 + off] = v;
    s += v; s2 += v * v;
  }
#pragma unroll
  for (int o = 16; o; o >>= 1) {
    s  += __shfl_down_sync(0xffffffffu, s, o);
    s2 += __shfl_down_sync(0xffffffffu, s2, o);
  }
  __shared__ float red[16];
  if ((t & 31) == 0) { red[(t >> 5) * 2] = s; red[(t >> 5) * 2 + 1] = s2; }
  __syncthreads();
  if (t == 0) {
    float ts = 0.f, ts2 = 0.f;
    for (int w = 0; w < 8; w++) { ts += red[w * 2]; ts2 += red[w * 2 + 1]; }
    atomicAdd(&g_sums[half * 2], ts);
    atomicAdd(&g_sums[half * 2 + 1], ts2);
  }
}

__global__ void k_norm_fe() {
  int t = threadIdx.x;
  int b = blockIdx.x >> 1;
  int half = blockIdx.x & 1;
  const float inv = 1.f / 1048576.f;
  float mu = g_sums[half * 2] * inv;
  float var = g_sums[half * 2 + 1] * inv - mu * mu;
  float rstd = rsqrtf(var + EPS);
#pragma unroll
  for (int q = 0; q < 4; q++) {
    int idx = b * 2048 + half * 1024 + t + q * 256;
    g_fe3[idx] = (g_fe3[idx] - mu) * rstd;
  }
}

// per (b): for each channel c: h = LN(relu(x@fi_w1+b1))*g+be ; impraw = h.fi_w2 + b2
__global__ void k_interact(const float* __restrict__ w1, const float* __restrict__ b1,
                           const float* __restrict__ gg, const float* __restrict__ be,
                           const float* __restrict__ w2, const float* __restrict__ b2f) {
  int b = blockIdx.x, t = threadIdx.x;   // 256
  int g = t >> 6, h = t & 63, w = t >> 5;
  __shared__ float w1s[64 * 65];
  __shared__ float xs[32 * 64];
  __shared__ float w2s[64];
  __shared__ float red[16];
  __shared__ float red2[8];
  for (int e = t; e < 4096; e += 256) w1s[(e >> 6) * 65 + (e & 63)] = w1[e];
  for (int e = t; e < 2048; e += 256) xs[e] = g_fe3[b * 2048 + e];
  if (t < 64) w2s[t] = w2[t];
  float b1v = b1[h], gv = gg[h], bev = be[h], b2v = b2f[0];
  __syncthreads();
  for (int it = 0; it < 8; it++) {
    int c = it * 4 + g;
    float hv = b1v;
#pragma unroll 16
    for (int i = 0; i < 64; i++) hv += xs[c * 64 + i] * w1s[i * 65 + h];
    hv = fmaxf(hv, 0.f);
    float s = hv, s2 = hv * hv;
#pragma unroll
    for (int o = 16; o; o >>= 1) {
      s  += __shfl_down_sync(0xffffffffu, s, o);
      s2 += __shfl_down_sync(0xffffffffu, s2, o);
    }
    if ((t & 31) == 0) { red[w * 2] = s; red[w * 2 + 1] = s2; }
    __syncthreads();
    float mu  = (red[g * 4] + red[g * 4 + 2]) * (1.f / 64.f);
    float var = (red[g * 4 + 1] + red[g * 4 + 3]) * (1.f / 64.f) - mu * mu;
    float rstd = rsqrtf(var + EPS);
    float hn = (hv - mu) * rstd * gv + bev;
    float pp = hn * w2s[h];
#pragma unroll
    for (int o = 16; o; o >>= 1) pp += __shfl_down_sync(0xffffffffu, pp, o);
    if ((t & 31) == 0) red2[w] = pp;
    __syncthreads();
    if (h == 0) g_impraw[b * 32 + c] = red2[g * 2] + red2[g * 2 + 1] + b2v;
    __syncthreads();
  }
}

__global__ void k_reduce_imp() {
  int t = threadIdx.x;
  float s = 0.f, s2 = 0.f;
  for (int e = blockIdx.x * 256 + t; e < NB * NCH; e += gridDim.x * 256) {
    float v = g_impraw[e]; s += v; s2 += v * v;
  }
#pragma unroll
  for (int o = 16; o; o >>= 1) {
    s  += __shfl_down_sync(0xffffffffu, s, o);
    s2 += __shfl_down_sync(0xffffffffu, s2, o);
  }
  __shared__ float red[16];
  if ((t & 31) == 0) { red[(t >> 5) * 2] = s; red[(t >> 5) * 2 + 1] = s2; }
  __syncthreads();
  if (t == 0) {
    float ts = 0.f, ts2 = 0.f;
    for (int w = 0; w < 8; w++) { ts += red[w * 2]; ts2 += red[w * 2 + 1]; }
    atomicAdd(&g_sums[4], ts);
    atomicAdd(&g_sums[5], ts2);
  }
}

__global__ void k_topk() {
  int b = blockIdx.x, t = threadIdx.x;  // 256
  __shared__ float imps[32];
  __shared__ float psm[32];
  const float inv = 1.f / (NB * NCH);
  float mu = g_sums[4] * inv;
  float var = g_sums[5] * inv - mu * mu;
  float rstd = rsqrtf(var + EPS);
  if (t < 32) {
    imps[t] = (g_impraw[b * 32 + t] - mu) * rstd;
    psm[t] = 0.f;
  }
  __syncthreads();
  if (t == 0) {
    float v[32];
    for (int c = 0; c < 32; c++) v[c] = imps[c];
    int chosen[KSEL]; float cv[KSEL];
    for (int k = 0; k < KSEL; k++) {
      float best = -1e30f; int bi = 0;
      for (int c = 0; c < 32; c++) if (v[c] > best) { best = v[c]; bi = c; }
      chosen[k] = bi; cv[k] = best; v[bi] = -1e30f;
    }
    float m = cv[0];
    float e[KSEL]; float sum = 0.f;
    for (int k = 0; k < KSEL; k++) { e[k] = expf(cv[k] - m); sum += e[k]; }
    float rs = 1.f / sum;
    for (int k = 0; k < KSEL; k++) psm[chosen[k]] = e[k] * rs;
    for (int a = 1; a < KSEL; a++) {           // sort ascending
      int key = chosen[a]; int j = a - 1;
      while (j >= 0 && chosen[j] > key) { chosen[j + 1] = chosen[j]; j--; }
      chosen[j + 1] = key;
    }
    for (int k = 0; k < KSEL; k++) g_idx[b * KSEL + k] = chosen[k];
  }
  __syncthreads();
  if (t < 32) g_p[b * 32 + t] = psm[t];
  for (int q = t; q < 2048; q += 256) g_fe3[b * 2048 + q] *= imps[q >> 6];
}

__global__ void k_compact() {
  int c = blockIdx.x;
  int lane = threadIdx.x;  // 32
  int cnt = 0;
  for (int b0 = 0; b0 < NB; b0 += 32) {
    int b = b0 + lane;
    bool sel = false;
#pragma unroll
    for (int k = 0; k < KSEL; k++) sel |= (g_idx[b * KSEL + k] == c);
    unsigned m = __ballot_sync(0xffffffffu, sel);
    if (sel) {
      int pos = cnt + __popc(m & ((1u << lane) - 1u));
      g_nodes[c * NB + pos] = b;
      g_loc[c * NB + b] = pos;
    }
    cnt += __popc(m);
  }
  if (lane == 0) g_cnt[c] = cnt;
}

// ---------------- generic NB x Kd x 64 GEMM, split-K into g_part ------------
__device__ __forceinline__ void gemm_body(const float* __restrict__ A,
                                          const float* __restrict__ W, int Kd) {
  __shared__ float As[64][65];
  __shared__ float Ws[64][68];
  int t = threadIdx.x;      // 256
  int m0 = blockIdx.x * 64;
  int r0 = (t >> 4) * 4;
  int c0 = (t & 15) * 4;
  float acc[4][4];
#pragma unroll
  for (int x = 0; x < 4; x++)
#pragma unroll
    for (int y = 0; y < 4; y++) acc[x][y] = 0.f;
  for (int ch = blockIdx.y; ch * 64 < Kd; ch += gridDim.y) {
    int k0 = ch * 64;
    for (int e = t; e < 4096; e += 256) {
      int r = e >> 6, kk = e & 63;
      As[r][kk] = A[(size_t)(m0 + r) * Kd + k0 + kk];
      Ws[r][kk] = W[(size_t)(k0 + r) * 64 + kk];
    }
    __syncthreads();
#pragma unroll 8
    for (int kk = 0; kk < 64; kk++) {
      float a0 = As[r0][kk], a1 = As[r0 + 1][kk], a2 = As[r0 + 2][kk], a3 = As[r0 + 3][kk];
      float4 w = *(const float4*)&Ws[kk][c0];
      acc[0][0] += a0 * w.x; acc[0][1] += a0 * w.y; acc[0][2] += a0 * w.z; acc[0][3] += a0 * w.w;
      acc[1][0] += a1 * w.x; acc[1][1] += a1 * w.y; acc[1][2] += a1 * w.z; acc[1][3] += a1 * w.w;
      acc[2][0] += a2 * w.x; acc[2][1] += a2 * w.y; acc[2][2] += a2 * w.z; acc[2][3] += a2 * w.w;
      acc[3][0] += a3 * w.x; acc[3][1] += a3 * w.y; acc[3][2] += a3 * w.z; acc[3][3] += a3 * w.w;
    }
    __syncthreads();
  }
  float* dst = &g_part[(size_t)blockIdx.y * (NB * NH)];
#pragma unroll
  for (int x = 0; x < 4; x++)
#pragma unroll
    for (int y = 0; y < 4; y++)
      dst[(size_t)(m0 + r0 + x) * 64 + c0 + y] = acc[x][y];
}

__global__ void k_gemm_feat(const float* __restrict__ W) { gemm_body(g_fe3, W, 2048); }
__global__ void k_gemm_head(const float* __restrict__ W) { gemm_body(g_full, W, 2560); }

__global__ void k_redpart(int which) {
  float* dst = which ? g_Hd : g_Y;
  for (int e = blockIdx.x * blockDim.x + threadIdx.x; e < NB * NH; e += gridDim.x * blockDim.x) {
    float s = 0.f;
#pragma unroll
    for (int sp = 0; sp < 16; sp++) s += g_part[sp * (NB * NH) + e];
    dst[e] = s;
  }
}

// ---------------- S = p.p^T - p_c p_c (compacted); track positive max -------
__global__ void k_S() {
  int c = blockIdx.y;
  int n = g_cnt[c];
  int i0 = blockIdx.x * 64;
  if (i0 >= n) return;
  __shared__ float pi[64 * 33];
  __shared__ float pj[64 * 33];
  __shared__ float redm[8];
  int t = threadIdx.x;  // 256
  for (int e = t; e < 2048; e += 256) {
    int r = e >> 5, k2 = e & 31;
    int gi = i0 + r; if (gi >= n) gi = n - 1;
    pi[r * 33 + k2] = g_p[g_nodes[c * NB + gi] * NCH + k2];
  }
  int ii0 = (t >> 4) * 4;
  int jj0 = (t & 15) * 4;
  float lmax = 0.f;
  float* slab = g_adj + ((size_t)c << 20);
  for (int j0 = 0; j0 < n; j0 += 64) {
    for (int e = t; e < 2048; e += 256) {
      int r = e >> 5, k2 = e & 31;
      int gj = j0 + r; if (gj >= n) gj = n - 1;
      pj[r * 33 + k2] = g_p[g_nodes[c * NB + gj] * NCH + k2];
    }
    __syncthreads();
    float acc[4][4];
#pragma unroll
    for (int x = 0; x < 4; x++)
#pragma unroll
      for (int y = 0; y < 4; y++) acc[x][y] = 0.f;
#pragma unroll 8
    for (int k2 = 0; k2 < 32; k2++) {
      float a[4], bb[4];
#pragma unroll
      for (int x = 0; x < 4; x++) a[x] = pi[(ii0 + x) * 33 + k2];
#pragma unroll
      for (int y = 0; y < 4; y++) bb[y] = pj[(jj0 + y) * 33 + k2];
#pragma unroll
      for (int x = 0; x < 4; x++)
#pragma unroll
        for (int y = 0; y < 4; y++) acc[x][y] += a[x] * bb[y];
    }
#pragma unroll
    for (int x = 0; x < 4; x++) {
      int gi = i0 + ii0 + x;
      if (gi < n) {
        float pic = pi[(ii0 + x) * 33 + c];
#pragma unroll
        for (int y = 0; y < 4; y++) {
          int gj = j0 + jj0 + y;
          if (gj < n) {
            float S = (gi == gj) ? 0.f : (acc[x][y] - pic * pj[(jj0 + y) * 33 + c]);
            slab[(size_t)gi * n + gj] = S;
            lmax = fmaxf(lmax, S);
          }
        }
      }
    }
    __syncthreads();
  }
#pragma unroll
  for (int o = 16; o; o >>= 1) lmax = fmaxf(lmax, __shfl_down_sync(0xffffffffu, lmax, o));
  if ((t & 31) == 0) redm[t >> 5] = lmax;
  __syncthreads();
  if (t == 0) {
    float m = 0.f;
    for (int w = 0; w < 8; w++) m = fmaxf(m, redm[w]);
    atomicMax(&g_mx[c], __float_as_int(m));
  }
}

__global__ void k_E() {
  int c = blockIdx.y;
  int n = g_cnt[c];
  int i = blockIdx.x;
  if (i >= n) return;
  int t = threadIdx.x;  // 128
  float mx = __int_as_float(g_mx[c]);
  float* row = g_adj + ((size_t)c << 20) + (size_t)i * n;
  float s = 0.f;
  for (int j = t; j < n; j += 128) {
    float S = row[j];
    float E = (S > 0.f) ? expf(S - mx) : 0.f;
    row[j] = E;
    s += E;
  }
#pragma unroll
  for (int o = 16; o; o >>= 1) s += __shfl_down_sync(0xffffffffu, s, o);
  __shared__ float red[4];
  if ((t & 31) == 0) red[t >> 5] = s;
  __syncthreads();
  if (t == 0) {
    float tot = red[0] + red[1] + red[2] + red[3];
    g_rowsum[c * NB + i] = tot;
    atomicAdd(&g_Z[c], tot);
  }
}

__global__ void k_dinv() {
  int c = blockIdx.x;
  int n = g_cnt[c];
  float Z = g_Z[c];
  float invZ = (Z > 0.f) ? 1.f / Z : 1.f;
  for (int i = threadIdx.x; i < n; i += blockDim.x)
    g_dinv[c * NB + i] = rsqrtf(1.f + g_rowsum[c * NB + i] * invZ);
}

__global__ void k_An() {
  int c = blockIdx.y;
  int n = g_cnt[c];
  int i = blockIdx.x;
  if (i >= n) return;
  float Z = g_Z[c];
  float invZ = (Z > 0.f) ? 1.f / Z : 1.f;
  float di = g_dinv[c * NB + i];
  float* row = g_adj + ((size_t)c << 20) + (size_t)i * n;
  for (int j = threadIdx.x; j < n; j += 128) {
    float v = row[j] * invZ * di * g_dinv[c * NB + j];
    if (j == i) v += di * di;
    row[j] = v;
  }
}

// GCN layer: X[i,h] = sum_j An[i,j]*Bmat[j,h] + bias[h]; relu; masked stats.
__global__ void k_gcn(const float* __restrict__ bias, int mode) {
  int c = blockIdx.y;
  int n = g_cnt[c];
  int i0 = blockIdx.x * 64;
  if (i0 >= n) return;
  __shared__ float As[64][65];
  __shared__ float Bs[64][68];
  int t = threadIdx.x;
  int r0 = (t >> 4) * 4, c0 = (t & 15) * 4;
  float acc[4][4];
#pragma unroll
  for (int x = 0; x < 4; x++)
#pragma unroll
    for (int y = 0; y < 4; y++) acc[x][y] = 0.f;
  const float* slab = g_adj + ((size_t)c << 20);
  for (int j0 = 0; j0 < n; j0 += 64) {
    for (int e = t; e < 4096; e += 256) {
      int r = e >> 6, kk = e & 63;
      int gi = i0 + r, gj = j0 + kk;
      As[r][kk] = (gi < n && gj < n) ? slab[(size_t)gi * n + gj] : 0.f;
      int jr = j0 + r;
      float bv = 0.f;
      if (jr < n)
        bv = (mode == 0) ? g_Y[g_nodes[c * NB + jr] * 64 + kk]
                         : g_T[((size_t)c * NB + jr) * 64 + kk];
      Bs[r][kk] = bv;
    }
    __syncthreads();
#pragma unroll 8
    for (int kk = 0; kk < 64; kk++) {
      float a0 = As[r0][kk], a1 = As[r0 + 1][kk], a2 = As[r0 + 2][kk], a3 = As[r0 + 3][kk];
      float4 w = *(const float4*)&Bs[kk][c0];
      acc[0][0] += a0 * w.x; acc[0][1] += a0 * w.y; acc[0][2] += a0 * w.z; acc[0][3] += a0 * w.w;
      acc[1][0] += a1 * w.x; acc[1][1] += a1 * w.y; acc[1][2] += a1 * w.z; acc[1][3] += a1 * w.w;
      acc[2][0] += a2 * w.x; acc[2][1] += a2 * w.y; acc[2][2] += a2 * w.z; acc[2][3] += a2 * w.w;
      acc[3][0] += a3 * w.x; acc[3][1] += a3 * w.y; acc[3][2] += a3 * w.z; acc[3][3] += a3 * w.w;
    }
    __syncthreads();
  }
  float s = 0.f, s2 = 0.f;
#pragma unroll
  for (int x = 0; x < 4; x++) {
    int gi = i0 + r0 + x;
    if (gi < n) {
#pragma unroll
      for (int y = 0; y < 4; y++) {
        float v = fmaxf(acc[x][y] + bias[c0 + y], 0.f);
        g_X1[((size_t)c * NB + gi) * 64 + c0 + y] = v;
        s += v; s2 += v * v;
      }
    }
  }
#pragma unroll
  for (int o = 16; o; o >>= 1) {
    s  += __shfl_down_sync(0xffffffffu, s, o);
    s2 += __shfl_down_sync(0xffffffffu, s2, o);
  }
  __shared__ float red[16];
  if ((t & 31) == 0) { red[(t >> 5) * 2] = s; red[(t >> 5) * 2 + 1] = s2; }
  __syncthreads();
  if (t == 0) {
    float ts = 0.f, ts2 = 0.f;
    for (int w = 0; w < 8; w++) { ts += red[w * 2]; ts2 += red[w * 2 + 1]; }
    float* st = mode ? g_stats2 : g_stats1;
    atomicAdd(&st[c * 2], ts);
    atomicAdd(&st[c * 2 + 1], ts2);
  }
}

// T = LN1(X1) @ gcn2_w  (per channel)
__global__ void k_lnmm(const float* __restrict__ W) {
  int c = blockIdx.y;
  int n = g_cnt[c];
  int i0 = blockIdx.x * 64;
  if (i0 >= n) return;
  __shared__ float As[64][65];
  __shared__ float Ws[64][68];
  int t = threadIdx.x;
  float cntf = (float)n * 64.f;
  float mu = g_stats1[c * 2] / cntf;
  float var = g_stats1[c * 2 + 1] / cntf - mu * mu;
  float rstd = rsqrtf(var + EPS);
  for (int e = t; e < 4096; e += 256) {
    int r = e >> 6, kk = e & 63;
    int gi = i0 + r;
    As[r][kk] = (gi < n) ? (g_X1[((size_t)c * NB + gi) * 64 + kk] - mu) * rstd : 0.f;
    Ws[r][kk] = W[r * 64 + kk];
  }
  __syncthreads();
  int r0 = (t >> 4) * 4, c0 = (t & 15) * 4;
  float acc[4][4];
#pragma unroll
  for (int x = 0; x < 4; x++)
#pragma unroll
    for (int y = 0; y < 4; y++) acc[x][y] = 0.f;
#pragma unroll 8
  for (int kk = 0; kk < 64; kk++) {
    float a0 = As[r0][kk], a1 = As[r0 + 1][kk], a2 = As[r0 + 2][kk], a3 = As[r0 + 3][kk];
    float4 w = *(const float4*)&Ws[kk][c0];
    acc[0][0] += a0 * w.x; acc[0][1] += a0 * w.y; acc[0][2] += a0 * w.z; acc[0][3] += a0 * w.w;
    acc[1][0] += a1 * w.x; acc[1][1] += a1 * w.y; acc[1][2] += a1 * w.z; acc[1][3] += a1 * w.w;
    acc[2][0] += a2 * w.x; acc[2][1] += a2 * w.y; acc[2][2] += a2 * w.z; acc[2][3] += a2 * w.w;
    acc[3][0] += a3 * w.x; acc[3][1] += a3 * w.y; acc[3][2] += a3 * w.z; acc[3][3] += a3 * w.w;
  }
#pragma unroll
  for (int x = 0; x < 4; x++) {
    int gi = i0 + r0 + x;
    if (gi < n)
#pragma unroll
      for (int y = 0; y < 4; y++)
        g_T[((size_t)c * NB + gi) * 64 + c0 + y] = acc[x][y];
  }
}

// build g_full = [gathered LN2(X2) (B,8,64) | scaled fe3 (B,2048)]
__global__ void k_gather() {
  int b = blockIdx.x, t = threadIdx.x;
  for (int q = t; q < 2560; q += 256) {
    float v;
    if (q < 512) {
      int k = q >> 6, h = q & 63;
      int c = g_idx[b * 8 + k];
      int ip = g_loc[c * NB + b];
      float cntf = (float)g_cnt[c] * 64.f;
      float mu = g_stats2[c * 2] / cntf;
      float var = g_stats2[c * 2 + 1] / cntf - mu * mu;
      float rstd = rsqrtf(var + EPS);
      v = (g_X1[((size_t)c * NB + ip) * 64 + h] - mu) * rstd;
    } else {
      v = g_fe3[b * 2048 + (q - 512)];
    }
    g_full[b * 2560 + q] = v;
  }
}

__global__ void k_head(const float* __restrict__ pb1, const float* __restrict__ pg,
                       const float* __restrict__ pbe, const float* __restrict__ pw2,
                       const float* __restrict__ pb2, float* __restrict__ out) {
  int b = blockIdx.x, t = threadIdx.x;  // 64
  float v = fmaxf(g_Hd[b * 64 + t] + pb1[t], 0.f);
  float s = v, s2 = v * v;
#pragma unroll
  for (int o = 16; o; o >>= 1) {
    s  += __shfl_down_sync(0xffffffffu, s, o);
    s2 += __shfl_down_sync(0xffffffffu, s2, o);
  }
  __shared__ float red[4];
  __shared__ float red2[4];
  if ((t & 31) == 0) { red[(t >> 5) * 2] = s; red[(t >> 5) * 2 + 1] = s2; }
  __syncthreads();
  float mu = (red[0] + red[2]) * (1.f / 64.f);
  float var = (red[1] + red[3]) * (1.f / 64.f) - mu * mu;
  float rstd = rsqrtf(var + EPS);
  float hn = (v - mu) * rstd * pg[t] + pbe[t];
  float o0 = hn * pw2[t * 2];
  float o1 = hn * pw2[t * 2 + 1];
#pragma unroll
  for (int o = 16; o; o >>= 1) {
    o0 += __shfl_down_sync(0xffffffffu, o0, o);
    o1 += __shfl_down_sync(0xffffffffu, o1, o);
  }
  if ((t & 31) == 0) { red2[(t >> 5) * 2] = o0; red2[(t >> 5) * 2 + 1] = o1; }
  __syncthreads();
  if (t == 0) {
    out[b * 2]     = red2[0] + red2[2] + pb2[0];
    out[b * 2 + 1] = red2[1] + red2[3] + pb2[1];
  }
}

// ---------------------------------------------------------------------------
extern "C" void kernel_launch(void* const* d_in, const int* in_sizes, int n_in,
                              void* d_out, int out_size) {
  const float* num_data = (const float*)d_in[0];
  const int*   cat_data = (const int*)d_in[1];
  const float* num_w    = (const float*)d_in[2];
  const float* num_b    = (const float*)d_in[3];
  const float* cat_emb  = (const float*)d_in[4];
  const float* fi_w1    = (const float*)d_in[5];
  const float* fi_b1    = (const float*)d_in[6];
  const float* fi_g     = (const float*)d_in[7];
  const float* fi_be    = (const float*)d_in[8];
  const float* fi_w2    = (const float*)d_in[9];
  const float* fi_b2    = (const float*)d_in[10];
  const float* gcn1_w   = (const float*)d_in[11];
  const float* gcn1_b   = (const float*)d_in[12];
  const float* gcn2_w   = (const float*)d_in[13];
  const float* gcn2_b   = (const float*)d_in[14];
  const float* pw1      = (const float*)d_in[15];
  const float* pb1      = (const float*)d_in[16];
  const float* pg       = (const float*)d_in[17];
  const float* pbe      = (const float*)d_in[18];
  const float* pw2      = (const float*)d_in[19];
  const float* pb2      = (const float*)d_in[20];

  k_init<<<1, 256>>>();
  k_fe<<<2048, 256>>>(num_data, cat_data, num_w, num_b, cat_emb);
  k_norm_fe<<<2048, 256>>>();
  k_interact<<<1024, 256>>>(fi_w1, fi_b1, fi_g, fi_be, fi_w2, fi_b2);
  k_reduce_imp<<<64, 256>>>();
  k_topk<<<1024, 256>>>();
  k_compact<<<32, 32>>>();
  k_gemm_feat<<<dim3(16, 16), 256>>>(gcn1_w);
  k_redpart<<<64, 256>>>(0);
  k_S<<<dim3(16, 32), 256>>>();
  k_E<<<dim3(1024, 32), 128>>>();
  k_dinv<<<32, 256>>>();
  k_An<<<dim3(1024, 32), 128>>>();
  k_gcn<<<dim3(16, 32), 256>>>(gcn1_b, 0);
  k_lnmm<<<dim3(16, 32), 256>>>(gcn2_w);
  k_gcn<<<dim3(16, 32), 256>>>(gcn2_b, 1);
  k_gather<<<1024, 256>>>();
  k_gemm_head<<<dim3(16, 16), 256>>>(pw1);
  k_redpart<<<64, 256>>>(1);
  k_head<<<1024, 64>>>(pb1, pg, pbe, pw2, pb2, (float*)d_out);
}

// round 3
// speedup vs baseline: 1.0663x; 1.0663x over previous
#include <cuda_runtime.h>
#include <cuda_bf16.h>
#include <math.h>

#define NB   1024
#define NNUM 16
#define NCAT 16
#define NCH  32
#define NH   64
#define NV   100
#define KSEL 8
#define EPS  1e-5f

// ---------------- scratch (static device globals; no allocs) ----------------
__device__ float g_fe3[NB * NCH * NH];            // 8MB (raw until k_topk scales+normalizes)
__device__ float g_impraw[NB * NCH];
__device__ float g_p[NB * NCH];
__device__ int   g_idx[NB * KSEL];
__device__ int   g_cnt[NCH];
__device__ int   g_nodes[NCH * NB];
__device__ int   g_loc[NCH * NB];
__device__ float g_Y[NB * NH];
__device__ float g_adj[(size_t)NCH * NB * NB];    // slab: S -> E -> An (compact rows)
__device__ int   g_mx[NCH];
__device__ float g_rowsum[NCH * NB];
__device__ float g_Z[NCH];
__device__ float g_dinv[NCH * NB];
__device__ float g_X1[NCH * NB * NH];
__device__ float g_T[NCH * NB * NH];
__device__ float g_stats1[NCH * 2];
__device__ float g_stats2[NCH * 2];
__device__ float g_sums[8];
__device__ float g_full[NB * (KSEL + NCH) * NH];
__device__ float g_Hd[NB * NH];
__device__ float g_part[16 * NB * NH];

// ---------------------------------------------------------------------------
__global__ void k_init() {
  int i = threadIdx.x;
  if (i < 8) g_sums[i] = 0.f;
  if (i < NCH) { g_cnt[i] = 0; g_mx[i] = 0; g_Z[i] = 0.f; }
  if (i < NCH * 2) { g_stats1[i] = 0.f; g_stats2[i] = 0.f; }
}

__global__ void k_fe(const float* __restrict__ num_data, const int* __restrict__ cat_data,
                     const float* __restrict__ num_w, const float* __restrict__ num_b,
                     const float* __restrict__ cat_emb) {
  int t = threadIdx.x;
  int b = blockIdx.x >> 1;
  int half = blockIdx.x & 1;
  float s = 0.f, s2 = 0.f;
#pragma unroll
  for (int q = 0; q < 4; q++) {
    int off = t + q * 256;
    int ch = off >> 6, h = off & 63;
    float v;
    if (half == 0) {
      v = num_data[b * NNUM + ch] * num_w[ch * NH + h] + num_b[ch * NH + h];
      v = fmaxf(v, 0.f);
    } else {
      v = cat_emb[((size_t)ch * NV + cat_data[b * NCAT + ch]) * NH + h];
    }
    g_fe3[b * 2048 + half * 1024 + off] = v;
    s += v; s2 += v * v;
  }
#pragma unroll
  for (int o = 16; o; o >>= 1) {
    s  += __shfl_down_sync(0xffffffffu, s, o);
    s2 += __shfl_down_sync(0xffffffffu, s2, o);
  }
  __shared__ float red[16];
  if ((t & 31) == 0) { red[(t >> 5) * 2] = s; red[(t >> 5) * 2 + 1] = s2; }
  __syncthreads();
  if (t == 0) {
    float ts = 0.f, ts2 = 0.f;
    for (int w = 0; w < 8; w++) { ts += red[w * 2]; ts2 += red[w * 2 + 1]; }
    atomicAdd(&g_sums[half * 2], ts);
    atomicAdd(&g_sums[half * 2 + 1], ts2);
  }
}

// Register-tiled interact: per block = one row b; 128 threads.
// thread (cg,hg): cg=t>>4 owns channels cg*4..+3, hg=t&15 owns h = hg*4..+3.
// Computes h = LN(relu(xn @ w1 + b1))*g+be, imp = h.w2 + b2, and accumulates
// global imp stats. xn = globally-normalized features (fused; g_fe3 stays raw).
__global__ void k_interact(const float* __restrict__ w1, const float* __restrict__ b1,
                           const float* __restrict__ gg, const float* __restrict__ be,
                           const float* __restrict__ w2, const float* __restrict__ b2f) {
  int b = blockIdx.x;
  int t = threadIdx.x;             // 128
  int cg = t >> 4, hg = t & 15;
  __shared__ float xsT[64][36];    // [i][c] transposed, padded
  __shared__ float w1s[64][68];    // [i][h]
  __shared__ float impsh[8][2];
  const float invN = 1.f / 1048576.f;
  float mu0 = g_sums[0] * invN;
  float rs0 = rsqrtf(g_sums[1] * invN - mu0 * mu0 + EPS);
  float mu1 = g_sums[2] * invN;
  float rs1 = rsqrtf(g_sums[3] * invN - mu1 * mu1 + EPS);
  for (int e = t; e < 4096; e += 128) w1s[e >> 6][e & 63] = w1[e];
  for (int e = t; e < 2048; e += 128) {
    int c = e >> 6, i = e & 63;
    float v = g_fe3[b * 2048 + e];
    xsT[i][c] = (c < 16) ? (v - mu0) * rs0 : (v - mu1) * rs1;
  }
  __syncthreads();
  float acc[4][4];
#pragma unroll
  for (int x = 0; x < 4; x++)
#pragma unroll
    for (int y = 0; y < 4; y++) acc[x][y] = 0.f;
#pragma unroll 16
  for (int kk = 0; kk < 64; kk++) {
    float4 a = *(const float4*)&xsT[kk][cg * 4];
    float4 w = *(const float4*)&w1s[kk][hg * 4];
    acc[0][0] += a.x * w.x; acc[0][1] += a.x * w.y; acc[0][2] += a.x * w.z; acc[0][3] += a.x * w.w;
    acc[1][0] += a.y * w.x; acc[1][1] += a.y * w.y; acc[1][2] += a.y * w.z; acc[1][3] += a.y * w.w;
    acc[2][0] += a.z * w.x; acc[2][1] += a.z * w.y; acc[2][2] += a.z * w.z; acc[2][3] += a.z * w.w;
    acc[3][0] += a.w * w.x; acc[3][1] += a.w * w.y; acc[3][2] += a.w * w.z; acc[3][3] += a.w * w.w;
  }
  int h0 = hg * 4;
  float4 b1v = *(const float4*)&b1[h0];
  float4 ggv = *(const float4*)&gg[h0];
  float4 bev = *(const float4*)&be[h0];
  float4 w2v = *(const float4*)&w2[h0];
  float b2v = b2f[0];
  float simp = 0.f, simp2 = 0.f;
#pragma unroll
  for (int x = 0; x < 4; x++) {
    float v0 = fmaxf(acc[x][0] + b1v.x, 0.f);
    float v1 = fmaxf(acc[x][1] + b1v.y, 0.f);
    float v2 = fmaxf(acc[x][2] + b1v.z, 0.f);
    float v3 = fmaxf(acc[x][3] + b1v.w, 0.f);
    float s  = v0 + v1 + v2 + v3;
    float s2 = v0 * v0 + v1 * v1 + v2 * v2 + v3 * v3;
#pragma unroll
    for (int o = 8; o; o >>= 1) {
      s  += __shfl_down_sync(0xffffffffu, s, o, 16);
      s2 += __shfl_down_sync(0xffffffffu, s2, o, 16);
    }
    s  = __shfl_sync(0xffffffffu, s, 0, 16);
    s2 = __shfl_sync(0xffffffffu, s2, 0, 16);
    float mu = s * (1.f / 64.f);
    float var = s2 * (1.f / 64.f) - mu * mu;
    float rstd = rsqrtf(var + EPS);
    float pp = ((v0 - mu) * rstd * ggv.x + bev.x) * w2v.x
             + ((v1 - mu) * rstd * ggv.y + bev.y) * w2v.y
             + ((v2 - mu) * rstd * ggv.z + bev.z) * w2v.z
             + ((v3 - mu) * rstd * ggv.w + bev.w) * w2v.w;
#pragma unroll
    for (int o = 8; o; o >>= 1) pp += __shfl_down_sync(0xffffffffu, pp, o, 16);
    if (hg == 0) {
      float val = pp + b2v;
      g_impraw[b * 32 + cg * 4 + x] = val;
      simp += val; simp2 += val * val;
    }
  }
  if (hg == 0) { impsh[cg][0] = simp; impsh[cg][1] = simp2; }
  __syncthreads();
  if (t == 0) {
    float a = 0.f, bsq = 0.f;
    for (int w = 0; w < 8; w++) { a += impsh[w][0]; bsq += impsh[w][1]; }
    atomicAdd(&g_sums[4], a);
    atomicAdd(&g_sums[5], bsq);
  }
}

__global__ void k_topk() {
  int b = blockIdx.x, t = threadIdx.x;  // 256
  __shared__ float imps[32];
  __shared__ float psm[32];
  const float inv = 1.f / (NB * NCH);
  float mu = g_sums[4] * inv;
  float var = g_sums[5] * inv - mu * mu;
  float rstd = rsqrtf(var + EPS);
  const float invN = 1.f / 1048576.f;
  float mu0 = g_sums[0] * invN;
  float rs0 = rsqrtf(g_sums[1] * invN - mu0 * mu0 + EPS);
  float mu1 = g_sums[2] * invN;
  float rs1 = rsqrtf(g_sums[3] * invN - mu1 * mu1 + EPS);
  if (t < 32) {
    imps[t] = (g_impraw[b * 32 + t] - mu) * rstd;
    psm[t] = 0.f;
  }
  __syncthreads();
  if (t == 0) {
    float v[32];
    for (int c = 0; c < 32; c++) v[c] = imps[c];
    int chosen[KSEL]; float cv[KSEL];
    for (int k = 0; k < KSEL; k++) {
      float best = -1e30f; int bi = 0;
      for (int c = 0; c < 32; c++) if (v[c] > best) { best = v[c]; bi = c; }
      chosen[k] = bi; cv[k] = best; v[bi] = -1e30f;
    }
    float m = cv[0];
    float e[KSEL]; float sum = 0.f;
    for (int k = 0; k < KSEL; k++) { e[k] = expf(cv[k] - m); sum += e[k]; }
    float rs = 1.f / sum;
    for (int k = 0; k < KSEL; k++) psm[chosen[k]] = e[k] * rs;
    for (int a = 1; a < KSEL; a++) {
      int key = chosen[a]; int j = a - 1;
      while (j >= 0 && chosen[j] > key) { chosen[j + 1] = chosen[j]; j--; }
      chosen[j + 1] = key;
    }
    for (int k = 0; k < KSEL; k++) g_idx[b * KSEL + k] = chosen[k];
  }
  __syncthreads();
  if (t < 32) g_p[b * 32 + t] = psm[t];
  for (int q = t; q < 2048; q += 256) {
    float raw = g_fe3[b * 2048 + q];
    float xn = (q < 1024) ? (raw - mu0) * rs0 : (raw - mu1) * rs1;
    g_fe3[b * 2048 + q] = xn * imps[q >> 6];
  }
}

__global__ void k_compact() {
  int c = blockIdx.x;
  int lane = threadIdx.x;  // 32
  int cnt = 0;
  for (int b0 = 0; b0 < NB; b0 += 32) {
    int b = b0 + lane;
    bool sel = false;
#pragma unroll
    for (int k = 0; k < KSEL; k++) sel |= (g_idx[b * KSEL + k] == c);
    unsigned m = __ballot_sync(0xffffffffu, sel);
    if (sel) {
      int pos = cnt + __popc(m & ((1u << lane) - 1u));
      g_nodes[c * NB + pos] = b;
      g_loc[c * NB + b] = pos;
    }
    cnt += __popc(m);
  }
  if (lane == 0) g_cnt[c] = cnt;
}

// ---------------- generic NB x Kd x 64 GEMM, split-K into g_part ------------
__device__ __forceinline__ void gemm_body(const float* __restrict__ A,
                                          const float* __restrict__ W, int Kd) {
  __shared__ float As[64][65];
  __shared__ float Ws[64][68];
  int t = threadIdx.x;      // 256
  int m0 = blockIdx.x * 64;
  int r0 = (t >> 4) * 4;
  int c0 = (t & 15) * 4;
  float acc[4][4];
#pragma unroll
  for (int x = 0; x < 4; x++)
#pragma unroll
    for (int y = 0; y < 4; y++) acc[x][y] = 0.f;
  for (int ch = blockIdx.y; ch * 64 < Kd; ch += gridDim.y) {
    int k0 = ch * 64;
    for (int e = t; e < 4096; e += 256) {
      int r = e >> 6, kk = e & 63;
      As[r][kk] = A[(size_t)(m0 + r) * Kd + k0 + kk];
      Ws[r][kk] = W[(size_t)(k0 + r) * 64 + kk];
    }
    __syncthreads();
#pragma unroll 8
    for (int kk = 0; kk < 64; kk++) {
      float a0 = As[r0][kk], a1 = As[r0 + 1][kk], a2 = As[r0 + 2][kk], a3 = As[r0 + 3][kk];
      float4 w = *(const float4*)&Ws[kk][c0];
      acc[0][0] += a0 * w.x; acc[0][1] += a0 * w.y; acc[0][2] += a0 * w.z; acc[0][3] += a0 * w.w;
      acc[1][0] += a1 * w.x; acc[1][1] += a1 * w.y; acc[1][2] += a1 * w.z; acc[1][3] += a1 * w.w;
      acc[2][0] += a2 * w.x; acc[2][1] += a2 * w.y; acc[2][2] += a2 * w.z; acc[2][3] += a2 * w.w;
      acc[3][0] += a3 * w.x; acc[3][1] += a3 * w.y; acc[3][2] += a3 * w.z; acc[3][3] += a3 * w.w;
    }
    __syncthreads();
  }
  float* dst = &g_part[(size_t)blockIdx.y * (NB * NH)];
#pragma unroll
  for (int x = 0; x < 4; x++)
#pragma unroll
    for (int y = 0; y < 4; y++)
      dst[(size_t)(m0 + r0 + x) * 64 + c0 + y] = acc[x][y];
}

__global__ void k_gemm_feat(const float* __restrict__ W) { gemm_body(g_fe3, W, 2048); }
__global__ void k_gemm_head(const float* __restrict__ W) { gemm_body(g_full, W, 2560); }

__global__ void k_redpart(int which) {
  float* dst = which ? g_Hd : g_Y;
  for (int e = blockIdx.x * blockDim.x + threadIdx.x; e < NB * NH; e += gridDim.x * blockDim.x) {
    float s = 0.f;
#pragma unroll
    for (int sp = 0; sp < 16; sp++) s += g_part[sp * (NB * NH) + e];
    dst[e] = s;
  }
}

// ---------------- S = p.p^T - p_c p_c (compacted); track positive max -------
__global__ void k_S() {
  int c = blockIdx.y;
  int n = g_cnt[c];
  int i0 = blockIdx.x * 64;
  if (i0 >= n) return;
  __shared__ float pi[64 * 33];
  __shared__ float pj[64 * 33];
  __shared__ float redm[8];
  int t = threadIdx.x;  // 256
  for (int e = t; e < 2048; e += 256) {
    int r = e >> 5, k2 = e & 31;
    int gi = i0 + r; if (gi >= n) gi = n - 1;
    pi[r * 33 + k2] = g_p[g_nodes[c * NB + gi] * NCH + k2];
  }
  int ii0 = (t >> 4) * 4;
  int jj0 = (t & 15) * 4;
  float lmax = 0.f;
  float* slab = g_adj + ((size_t)c << 20);
  for (int j0 = 0; j0 < n; j0 += 64) {
    for (int e = t; e < 2048; e += 256) {
      int r = e >> 5, k2 = e & 31;
      int gj = j0 + r; if (gj >= n) gj = n - 1;
      pj[r * 33 + k2] = g_p[g_nodes[c * NB + gj] * NCH + k2];
    }
    __syncthreads();
    float acc[4][4];
#pragma unroll
    for (int x = 0; x < 4; x++)
#pragma unroll
      for (int y = 0; y < 4; y++) acc[x][y] = 0.f;
#pragma unroll 8
    for (int k2 = 0; k2 < 32; k2++) {
      float a[4], bb[4];
#pragma unroll
      for (int x = 0; x < 4; x++) a[x] = pi[(ii0 + x) * 33 + k2];
#pragma unroll
      for (int y = 0; y < 4; y++) bb[y] = pj[(jj0 + y) * 33 + k2];
#pragma unroll
      for (int x = 0; x < 4; x++)
#pragma unroll
        for (int y = 0; y < 4; y++) acc[x][y] += a[x] * bb[y];
    }
#pragma unroll
    for (int x = 0; x < 4; x++) {
      int gi = i0 + ii0 + x;
      if (gi < n) {
        float pic = pi[(ii0 + x) * 33 + c];
#pragma unroll
        for (int y = 0; y < 4; y++) {
          int gj = j0 + jj0 + y;
          if (gj < n) {
            float S = (gi == gj) ? 0.f : (acc[x][y] - pic * pj[(jj0 + y) * 33 + c]);
            slab[(size_t)gi * n + gj] = S;
            lmax = fmaxf(lmax, S);
          }
        }
      }
    }
    __syncthreads();
  }
#pragma unroll
  for (int o = 16; o; o >>= 1) lmax = fmaxf(lmax, __shfl_down_sync(0xffffffffu, lmax, o));
  if ((t & 31) == 0) redm[t >> 5] = lmax;
  __syncthreads();
  if (t == 0) {
    float m = 0.f;
    for (int w = 0; w < 8; w++) m = fmaxf(m, redm[w]);
    atomicMax(&g_mx[c], __float_as_int(m));
  }
}

__global__ void k_E() {
  int c = blockIdx.y;
  int n = g_cnt[c];
  int i = blockIdx.x;
  if (i >= n) return;
  int t = threadIdx.x;  // 128
  float mx = __int_as_float(g_mx[c]);
  float* row = g_adj + ((size_t)c << 20) + (size_t)i * n;
  float s = 0.f;
  for (int j = t; j < n; j += 128) {
    float S = row[j];
    float E = (S > 0.f) ? __expf(S - mx) : 0.f;
    row[j] = E;
    s += E;
  }
#pragma unroll
  for (int o = 16; o; o >>= 1) s += __shfl_down_sync(0xffffffffu, s, o);
  __shared__ float red[4];
  if ((t & 31) == 0) red[t >> 5] = s;
  __syncthreads();
  if (t == 0) {
    float tot = red[0] + red[1] + red[2] + red[3];
    g_rowsum[c * NB + i] = tot;
    atomicAdd(&g_Z[c], tot);
  }
}

__global__ void k_dinv() {
  int c = blockIdx.x;
  int n = g_cnt[c];
  float Z = g_Z[c];
  float invZ = (Z > 0.f) ? 1.f / Z : 1.f;
  for (int i = threadIdx.x; i < n; i += blockDim.x)
    g_dinv[c * NB + i] = rsqrtf(1.f + g_rowsum[c * NB + i] * invZ);
}

__global__ void k_An() {
  int c = blockIdx.y;
  int n = g_cnt[c];
  int i = blockIdx.x;
  if (i >= n) return;
  float Z = g_Z[c];
  float invZ = (Z > 0.f) ? 1.f / Z : 1.f;
  float di = g_dinv[c * NB + i];
  float* row = g_adj + ((size_t)c << 20) + (size_t)i * n;
  for (int j = threadIdx.x; j < n; j += 128) {
    float v = row[j] * invZ * di * g_dinv[c * NB + j];
    if (j == i) v += di * di;
    row[j] = v;
  }
}

// GCN layer: X[i,h] = sum_j An[i,j]*Bmat[j,h] + bias[h]; relu; masked stats.
__global__ void k_gcn(const float* __restrict__ bias, int mode) {
  int c = blockIdx.y;
  int n = g_cnt[c];
  int i0 = blockIdx.x * 64;
  if (i0 >= n) return;
  __shared__ float As[64][65];
  __shared__ float Bs[64][68];
  int t = threadIdx.x;
  int r0 = (t >> 4) * 4, c0 = (t & 15) * 4;
  float acc[4][4];
#pragma unroll
  for (int x = 0; x < 4; x++)
#pragma unroll
    for (int y = 0; y < 4; y++) acc[x][y] = 0.f;
  const float* slab = g_adj + ((size_t)c << 20);
  for (int j0 = 0; j0 < n; j0 += 64) {
    for (int e = t; e < 4096; e += 256) {
      int r = e >> 6, kk = e & 63;
      int gi = i0 + r, gj = j0 + kk;
      As[r][kk] = (gi < n && gj < n) ? slab[(size_t)gi * n + gj] : 0.f;
      int jr = j0 + r;
      float bv = 0.f;
      if (jr < n)
        bv = (mode == 0) ? g_Y[g_nodes[c * NB + jr] * 64 + kk]
                         : g_T[((size_t)c * NB + jr) * 64 + kk];
      Bs[r][kk] = bv;
    }
    __syncthreads();
#pragma unroll 8
    for (int kk = 0; kk < 64; kk++) {
      float a0 = As[r0][kk], a1 = As[r0 + 1][kk], a2 = As[r0 + 2][kk], a3 = As[r0 + 3][kk];
      float4 w = *(const float4*)&Bs[kk][c0];
      acc[0][0] += a0 * w.x; acc[0][1] += a0 * w.y; acc[0][2] += a0 * w.z; acc[0][3] += a0 * w.w;
      acc[1][0] += a1 * w.x; acc[1][1] += a1 * w.y; acc[1][2] += a1 * w.z; acc[1][3] += a1 * w.w;
      acc[2][0] += a2 * w.x; acc[2][1] += a2 * w.y; acc[2][2] += a2 * w.z; acc[2][3] += a2 * w.w;
      acc[3][0] += a3 * w.x; acc[3][1] += a3 * w.y; acc[3][2] += a3 * w.z; acc[3][3] += a3 * w.w;
    }
    __syncthreads();
  }
  float s = 0.f, s2 = 0.f;
#pragma unroll
  for (int x = 0; x < 4; x++) {
    int gi = i0 + r0 + x;
    if (gi < n) {
#pragma unroll
      for (int y = 0; y < 4; y++) {
        float v = fmaxf(acc[x][y] + bias[c0 + y], 0.f);
        g_X1[((size_t)c * NB + gi) * 64 + c0 + y] = v;
        s += v; s2 += v * v;
      }
    }
  }
#pragma unroll
  for (int o = 16; o; o >>= 1) {
    s  += __shfl_down_sync(0xffffffffu, s, o);
    s2 += __shfl_down_sync(0xffffffffu, s2, o);
  }
  __shared__ float red[16];
  if ((t & 31) == 0) { red[(t >> 5) * 2] = s; red[(t >> 5) * 2 + 1] = s2; }
  __syncthreads();
  if (t == 0) {
    float ts = 0.f, ts2 = 0.f;
    for (int w = 0; w < 8; w++) { ts += red[w * 2]; ts2 += red[w * 2 + 1]; }
    float* st = mode ? g_stats2 : g_stats1;
    atomicAdd(&st[c * 2], ts);
    atomicAdd(&st[c * 2 + 1], ts2);
  }
}

// T = LN1(X1) @ gcn2_w  (per channel)
__global__ void k_lnmm(const float* __restrict__ W) {
  int c = blockIdx.y;
  int n = g_cnt[c];
  int i0 = blockIdx.x * 64;
  if (i0 >= n) return;
  __shared__ float As[64][65];
  __shared__ float Ws[64][68];
  int t = threadIdx.x;
  float cntf = (float)n * 64.f;
  float mu = g_stats1[c * 2] / cntf;
  float var = g_stats1[c * 2 + 1] / cntf - mu * mu;
  float rstd = rsqrtf(var + EPS);
  for (int e = t; e < 4096; e += 256) {
    int r = e >> 6, kk = e & 63;
    int gi = i0 + r;
    As[r][kk] = (gi < n) ? (g_X1[((size_t)c * NB + gi) * 64 + kk] - mu) * rstd : 0.f;
    Ws[r][kk] = W[r * 64 + kk];
  }
  __syncthreads();
  int r0 = (t >> 4) * 4, c0 = (t & 15) * 4;
  float acc[4][4];
#pragma unroll
  for (int x = 0; x < 4; x++)
#pragma unroll
    for (int y = 0; y < 4; y++) acc[x][y] = 0.f;
#pragma unroll 8
  for (int kk = 0; kk < 64; kk++) {
    float a0 = As[r0][kk], a1 = As[r0 + 1][kk], a2 = As[r0 + 2][kk], a3 = As[r0 + 3][kk];
    float4 w = *(const float4*)&Ws[kk][c0];
    acc[0][0] += a0 * w.x; acc[0][1] += a0 * w.y; acc[0][2] += a0 * w.z; acc[0][3] += a0 * w.w;
    acc[1][0] += a1 * w.x; acc[1][1] += a1 * w.y; acc[1][2] += a1 * w.z; acc[1][3] += a1 * w.w;
    acc[2][0] += a2 * w.x; acc[2][1] += a2 * w.y; acc[2][2] += a2 * w.z; acc[2][3] += a2 * w.w;
    acc[3][0] += a3 * w.x; acc[3][1] += a3 * w.y; acc[3][2] += a3 * w.z; acc[3][3] += a3 * w.w;
  }
#pragma unroll
  for (int x = 0; x < 4; x++) {
    int gi = i0 + r0 + x;
    if (gi < n)
#pragma unroll
      for (int y = 0; y < 4; y++)
        g_T[((size_t)c * NB + gi) * 64 + c0 + y] = acc[x][y];
  }
}

// build g_full = [gathered LN2(X2) (B,8,64) | scaled fe3 (B,2048)]
__global__ void k_gather() {
  int b = blockIdx.x, t = threadIdx.x;
  for (int q = t; q < 2560; q += 256) {
    float v;
    if (q < 512) {
      int k = q >> 6, h = q & 63;
      int c = g_idx[b * 8 + k];
      int ip = g_loc[c * NB + b];
      float cntf = (float)g_cnt[c] * 64.f;
      float mu = g_stats2[c * 2] / cntf;
      float var = g_stats2[c * 2 + 1] / cntf - mu * mu;
      float rstd = rsqrtf(var + EPS);
      v = (g_X1[((size_t)c * NB + ip) * 64 + h] - mu) * rstd;
    } else {
      v = g_fe3[b * 2048 + (q - 512)];
    }
    g_full[b * 2560 + q] = v;
  }
}

__global__ void k_head(const float* __restrict__ pb1, const float* __restrict__ pg,
                       const float* __restrict__ pbe, const float* __restrict__ pw2,
                       const float* __restrict__ pb2, float* __restrict__ out) {
  int b = blockIdx.x, t = threadIdx.x;  // 64
  float v = fmaxf(g_Hd[b * 64 + t] + pb1[t], 0.f);
  float s = v, s2 = v * v;
#pragma unroll
  for (int o = 16; o; o >>= 1) {
    s  += __shfl_down_sync(0xffffffffu, s, o);
    s2 += __shfl_down_sync(0xffffffffu, s2, o);
  }
  __shared__ float red[4];
  __shared__ float red2[4];
  if ((t & 31) == 0) { red[(t >> 5) * 2] = s; red[(t >> 5) * 2 + 1] = s2; }
  __syncthreads();
  float mu = (red[0] + red[2]) * (1.f / 64.f);
  float var = (red[1] + red[3]) * (1.f / 64.f) - mu * mu;
  float rstd = rsqrtf(var + EPS);
  float hn = (v - mu) * rstd * pg[t] + pbe[t];
  float o0 = hn * pw2[t * 2];
  float o1 = hn * pw2[t * 2 + 1];
#pragma unroll
  for (int o = 16; o; o >>= 1) {
    o0 += __shfl_down_sync(0xffffffffu, o0, o);
    o1 += __shfl_down_sync(0xffffffffu, o1, o);
  }
  if ((t & 31) == 0) { red2[(t >> 5) * 2] = o0; red2[(t >> 5) * 2 + 1] = o1; }
  __syncthreads();
  if (t == 0) {
    out[b * 2]     = red2[0] + red2[2] + pb2[0];
    out[b * 2 + 1] = red2[1] + red2[3] + pb2[1];
  }
}

// ---------------------------------------------------------------------------
extern "C" void kernel_launch(void* const* d_in, const int* in_sizes, int n_in,
                              void* d_out, int out_size) {
  const float* num_data = (const float*)d_in[0];
  const int*   cat_data = (const int*)d_in[1];
  const float* num_w    = (const float*)d_in[2];
  const float* num_b    = (const float*)d_in[3];
  const float* cat_emb  = (const float*)d_in[4];
  const float* fi_w1    = (const float*)d_in[5];
  const float* fi_b1    = (const float*)d_in[6];
  const float* fi_g     = (const float*)d_in[7];
  const float* fi_be    = (const float*)d_in[8];
  const float* fi_w2    = (const float*)d_in[9];
  const float* fi_b2    = (const float*)d_in[10];
  const float* gcn1_w   = (const float*)d_in[11];
  const float* gcn1_b   = (const float*)d_in[12];
  const float* gcn2_w   = (const float*)d_in[13];
  const float* gcn2_b   = (const float*)d_in[14];
  const float* pw1      = (const float*)d_in[15];
  const float* pb1      = (const float*)d_in[16];
  const float* pg       = (const float*)d_in[17];
  const float* pbe      = (const float*)d_in[18];
  const float* pw2      = (const float*)d_in[19];
  const float* pb2      = (const float*)d_in[20];

  k_init<<<1, 256>>>();
  k_fe<<<2048, 256>>>(num_data, cat_data, num_w, num_b, cat_emb);
  k_interact<<<1024, 128>>>(fi_w1, fi_b1, fi_g, fi_be, fi_w2, fi_b2);
  k_topk<<<1024, 256>>>();
  k_compact<<<32, 32>>>();
  k_gemm_feat<<<dim3(16, 16), 256>>>(gcn1_w);
  k_redpart<<<64, 256>>>(0);
  k_S<<<dim3(16, 32), 256>>>();
  k_E<<<dim3(1024, 32), 128>>>();
  k_dinv<<<32, 256>>>();
  k_An<<<dim3(1024, 32), 128>>>();
  k_gcn<<<dim3(16, 32), 256>>>(gcn1_b, 0);
  k_lnmm<<<dim3(16, 32), 256>>>(gcn2_w);
  k_gcn<<<dim3(16, 32), 256>>>(gcn2_b, 1);
  k_gather<<<1024, 256>>>();
  k_gemm_head<<<dim3(16, 16), 256>>>(pw1);
  k_redpart<<<64, 256>>>(1);
  k_head<<<1024, 64>>>(pb1, pg, pbe, pw2, pb2, (float*)d_out);
}